// round 4
// baseline (speedup 1.0000x reference)
#include <cuda_runtime.h>
#include <math.h>

typedef unsigned long long ull;

// Problem constants
#define NB 8
#define SQ 4096
#define EE 1024
#define HH 16
#define NCHUNK 16
#define CHUNK 256

// Scratch (static device globals -- allocation-free per harness rules)
__device__ float g_qvec[EE];
__device__ float g_wqk[HH*EE];
__device__ float g_c[HH];
__device__ float g_logits[NB*HH*SQ];
__device__ float g_pm[NB*HH*SQ];
__device__ float g_A[NB*HH*SQ];
__device__ float g_psum[NB*HH];
__device__ float g_partial[NB*NCHUNK*HH*EE];   // 8 MB partial ctx
__device__ float g_ctx[NB*HH*EE];
__device__ float g_hidden[NB*EE];
__device__ float g_act[NB*4*EE];

__device__ __forceinline__ float warp_sum(float v){
    #pragma unroll
    for (int o=16;o;o>>=1) v += __shfl_xor_sync(0xffffffffu, v, o);
    return v;
}

// packed f32x2 helpers
__device__ __forceinline__ void ffma2(ull &d, ull a, ull b){
    asm("fma.rn.f32x2 %0, %1, %2, %0;" : "+l"(d) : "l"(a), "l"(b));
}
__device__ __forceinline__ ull fadd2(ull a, ull b){
    ull d; asm("add.rn.f32x2 %0, %1, %2;" : "=l"(d) : "l"(a), "l"(b)); return d;
}
__device__ __forceinline__ ull pk2(float x, float y){
    float2 t = make_float2(x,y); return *(ull*)&t;
}
__device__ __forceinline__ float2 upk(ull v){ return *(float2*)&v; }

__device__ __forceinline__ void cpa16(void* s, const void* g){
    unsigned sa = (unsigned)__cvta_generic_to_shared(s);
    asm volatile("cp.async.cg.shared.global [%0],[%1],16;"::"r"(sa),"l"(g));
}

__global__ void k_dummy(){}

// ---------------- K0a: qvec = Wq @ query + bq ----------------
__global__ void __launch_bounds__(256) k_qvec(const float4* __restrict__ Wq4,
                                              const float4* __restrict__ q4,
                                              const float*  __restrict__ bq){
    int lane = threadIdx.x & 31, warp = threadIdx.x >> 5;
    int row = blockIdx.x*8 + warp;
    float acc = 0.f;
    #pragma unroll
    for (int k=0;k<8;k++){
        float4 w = Wq4[row*256 + lane + 32*k];
        float4 q = q4[lane + 32*k];
        acc += w.x*q.x + w.y*q.y + w.z*q.z + w.w*q.w;
    }
    acc = warp_sum(acc);
    if (lane==0) g_qvec[row] = acc + bq[row];
}

// ---------------- K0b: w_qk[h,e] = 0.125*sum_d qv[d]*Wk[h*64+d,e]; c[h] ----------------
// 128 blocks = 16 h x 8 e-slices (128 floats each)
__global__ void __launch_bounds__(256) k_wqk(const float4* __restrict__ Wk4,
                                             const float*  __restrict__ bk){
    __shared__ float qv[64];
    __shared__ float4 red[8][32];
    int h = blockIdx.x>>3, es = blockIdx.x&7;
    int tid = threadIdx.x, col = tid&31, dg = tid>>5;
    if (tid < 64) qv[tid] = g_qvec[h*64+tid];
    __syncthreads();
    float4 acc = make_float4(0.f,0.f,0.f,0.f);
    #pragma unroll
    for (int j=0;j<8;j++){
        int d = dg*8+j;
        float w = qv[d];
        float4 kk = Wk4[(h*64+d)*256 + es*32 + col];
        acc.x += w*kk.x; acc.y += w*kk.y; acc.z += w*kk.z; acc.w += w*kk.w;
    }
    red[dg][col] = acc;
    __syncthreads();
    if (tid < 32){
        float4 s = red[0][tid];
        #pragma unroll
        for (int g=1;g<8;g++){
            float4 r = red[g][tid];
            s.x+=r.x; s.y+=r.y; s.z+=r.z; s.w+=r.w;
        }
        s.x*=0.125f; s.y*=0.125f; s.z*=0.125f; s.w*=0.125f;
        ((float4*)g_wqk)[h*256 + es*32 + tid] = s;
    }
    if (es==0 && tid==0){
        float c=0.f;
        for (int d=0;d<64;d++) c += qv[d]*bk[h*64+d];
        g_c[h] = 0.125f*c;
    }
}

// ---------------- K1: logits = w_qk·x + c  (pass 1 over x) ----------------
// 8 warps = 4 e-quarters x 2 head-octets. w_qk in 64 registers for the whole
// kernel. 4-row tiles double-buffered via cp.async. Packed butterfly fold.
__global__ void __launch_bounds__(256,1) k_logits(const float4* __restrict__ x4){
    __shared__ float4 sx[2][1024];     // 32KB double buffer, 4 rows each
    __shared__ float  sred[3][64];
    int tid = threadIdx.x, lane = tid&31, warp = tid>>5;
    int eq = warp>>1, ho = warp&1;
    const ull* wq = (const ull*)g_wqk;
    ull w0[2][8], w1[2][8];
    #pragma unroll
    for (int st=0; st<2; st++)
        #pragma unroll
        for (int hp=0; hp<8; hp++){
            int off = (ho*8+hp)*512 + eq*128 + st*64 + lane*2;
            w0[st][hp] = wq[off];
            w1[st][hp] = wq[off+1];
        }
    float ch = g_c[ho*8 + (lane&7)];
    int rowbase = blockIdx.x*32;
    int b = rowbase>>12;

    // prefetch tile 0
    #pragma unroll
    for (int i=0;i<4;i++) cpa16(&sx[0][i*256+tid], &x4[(rowbase+i)*256 + tid]);
    asm volatile("cp.async.commit_group;");

    for (int t=0;t<8;t++){
        if (t<7){
            int rb1 = rowbase + (t+1)*4;
            #pragma unroll
            for (int i=0;i<4;i++) cpa16(&sx[(t+1)&1][i*256+tid], &x4[(rb1+i)*256 + tid]);
            asm volatile("cp.async.commit_group;");
            asm volatile("cp.async.wait_group 1;");
        } else {
            asm volatile("cp.async.wait_group 0;");
        }
        __syncthreads();
        const float4* xs = sx[t&1];
        ull a[32];
        #pragma unroll
        for (int j=0;j<32;j++) a[j] = 0ULL;
        #pragma unroll
        for (int i=0;i<4;i++){
            #pragma unroll
            for (int st=0; st<2; st++){
                float4 xv = xs[i*256 + eq*64 + st*32 + lane];
                ull x01 = pk2(xv.x,xv.y), x23 = pk2(xv.z,xv.w);
                #pragma unroll
                for (int hp=0;hp<8;hp++){
                    ffma2(a[i*8+hp], w0[st][hp], x01);
                    ffma2(a[i*8+hp], w1[st][hp], x23);
                }
            }
        }
        // packed butterfly fold: lane L ends with packed sum of value L
        #pragma unroll
        for (int s=16; s>0; s>>=1){
            #pragma unroll
            for (int j=0;j<s;j++){
                ull t2 = (lane & s) ? a[j] : a[j+s];
                t2 = __shfl_xor_sync(0xffffffffu, t2, s);
                ull keep = (lane & s) ? a[j+s] : a[j];
                a[j] = fadd2(keep, t2);
            }
        }
        float2 f = upk(a[0]);
        float v = f.x + f.y;
        if (eq > 0) sred[eq-1][ho*32 + lane] = v;
        __syncthreads();
        if (eq == 0){
            int rb = rowbase + t*4;
            v += sred[0][ho*32+lane] + sred[1][ho*32+lane] + sred[2][ho*32+lane] + ch;
            int row = rb + (lane>>3);
            int h = ho*8 + (lane&7);
            g_logits[((b<<4)+h)*4096 + (row & 4095)] = v;
        }
        __syncthreads();
    }
}

// ---------------- K2: softmax over S + gumbel hard mask, per (b,h) ----------------
__global__ void __launch_bounds__(256) k_softmax(const float2* __restrict__ gu2){
    __shared__ float red[8];
    __shared__ float bc;
    int bid = blockIdx.x;                 // b*16+h
    int tid = threadIdx.x, lane = tid&31, warp = tid>>5;
    int base = bid*4096;
    float l[16];
    float m = -1e30f;
    #pragma unroll
    for (int j=0;j<16;j++){ l[j] = g_logits[base + tid + 256*j]; m = fmaxf(m, l[j]); }
    #pragma unroll
    for (int o=16;o;o>>=1) m = fmaxf(m, __shfl_xor_sync(0xffffffffu,m,o));
    if (lane==0) red[warp]=m;
    __syncthreads();
    if (tid==0){ float mm=red[0]; for(int i=1;i<8;i++) mm=fmaxf(mm,red[i]); bc=mm; }
    __syncthreads();
    m = bc;
    float ex[16]; float sum=0.f;
    #pragma unroll
    for (int j=0;j<16;j++){ ex[j]=__expf(l[j]-m); sum+=ex[j]; }
    sum = warp_sum(sum);
    if (lane==0) red[warp]=sum;
    __syncthreads();
    if (tid==0){ float ss=0.f; for(int i=0;i<8;i++) ss+=red[i]; bc=ss; }
    __syncthreads();
    float inv = 1.f/bc;
    float ps=0.f;
    #pragma unroll
    for (int j=0;j<16;j++){
        int s = tid+256*j;
        float prob = ex[j]*inv;
        float2 u = gu2[base+s];
        float g0 = -__logf(-__logf(u.x+1e-20f)+1e-20f);
        float g1 = -__logf(-__logf(u.y+1e-20f)+1e-20f);
        float A = (l[j]+g1 > g0) ? 1.f : 0.f;
        float pm = A*prob;
        g_A[base+s]=A; g_pm[base+s]=pm; ps+=pm;
    }
    ps = warp_sum(ps);
    if (lane==0) red[warp]=ps;
    __syncthreads();
    if (tid==0){ float ss=0.f; for(int i=0;i<8;i++) ss+=red[i]; g_psum[bid]=ss; }
}

// ---------------- K2b: masks/attn = sum over heads (float4, h quartered) ----------------
__global__ void __launch_bounds__(256) k_sums(float* __restrict__ out){
    __shared__ float4 sA[4][64], sP[4][64];
    int tid = threadIdx.x;
    int t = tid>>2, q = tid&3;
    int sf4 = blockIdx.x*64 + t;         // global s-float4 index (0..8191)
    int b = sf4>>10, f = sf4&1023;
    const float4* A4 = (const float4*)g_A;
    const float4* P4 = (const float4*)g_pm;
    float4 ms = make_float4(0,0,0,0), as = make_float4(0,0,0,0);
    #pragma unroll
    for (int hh=0; hh<4; hh++){
        int h = q*4+hh;
        int off = ((b<<4)+h)*1024 + f;
        float4 av = A4[off], pv = P4[off];
        ms.x+=av.x; ms.y+=av.y; ms.z+=av.z; ms.w+=av.w;
        as.x+=pv.x; as.y+=pv.y; as.z+=pv.z; as.w+=pv.w;
    }
    if (q){ sA[q][t]=ms; sP[q][t]=as; }
    __syncthreads();
    if (q==0){
        #pragma unroll
        for (int g=1;g<4;g++){
            float4 av = sA[g][t], pv = sP[g][t];
            ms.x+=av.x; ms.y+=av.y; ms.z+=av.z; ms.w+=av.w;
            as.x+=pv.x; as.y+=pv.y; as.z+=pv.z; as.w+=pv.w;
        }
        float4* out4 = (float4*)out;
        out4[2048 + sf4] = ms;           // masks @ out[8192]
        out4[10240 + sf4] = as;          // attn  @ out[40960]
    }
}

// ---------------- K3: ctx partials (pass 2 over x), f32x2, 128 blocks ----------------
__global__ void __launch_bounds__(256,2) k_ctx(const float4* __restrict__ x4){
    __shared__ float2 spm[16*CHUNK];   // (p,p) duplicated for packed FMA
    int tid = threadIdx.x;
    int b = blockIdx.x >> 4, chunk = blockIdx.x & 15;
    int s0 = chunk*CHUNK;
    #pragma unroll
    for (int i=0;i<16;i++){
        int idx = tid + 256*i;
        int h = idx>>8, si = idx&255;
        float p = g_pm[((b<<4)+h)*4096 + s0 + si];
        spm[idx] = make_float2(p,p);
    }
    __syncthreads();
    ull acc[16][2];
    #pragma unroll
    for (int h=0;h<16;h++){ acc[h][0]=0ULL; acc[h][1]=0ULL; }
    #pragma unroll 2
    for (int si=0; si<CHUNK; si++){
        float4 xv = x4[(b*4096 + s0 + si)*256 + tid];
        ull x01 = pk2(xv.x,xv.y), x23 = pk2(xv.z,xv.w);
        #pragma unroll
        for (int h=0;h<16;h++){
            ull p = *(ull*)&spm[h*CHUNK+si];
            ffma2(acc[h][0], p, x01);
            ffma2(acc[h][1], p, x23);
        }
    }
    float4* p4 = (float4*)g_partial;
    #pragma unroll
    for (int h=0;h<16;h++){
        float2 lo = upk(acc[h][0]), hi = upk(acc[h][1]);
        p4[((b*NCHUNK+chunk)*16 + h)*256 + tid] = make_float4(lo.x,lo.y,hi.x,hi.y);
    }
}

// ---------------- K3r: deterministic reduction of ctx partials (float4) ----------------
__global__ void __launch_bounds__(256) k_ctxr(){
    int f4 = blockIdx.x*256 + threadIdx.x;   // 0..32767 float4 of ctx
    int b = f4>>12, rem = f4&4095;
    const float4* p4 = (const float4*)g_partial;
    float4 s = make_float4(0,0,0,0);
    #pragma unroll
    for (int c=0;c<NCHUNK;c++){
        float4 v = p4[((b*NCHUNK+c)<<12) + rem];
        s.x+=v.x; s.y+=v.y; s.z+=v.z; s.w+=v.w;
    }
    ((float4*)g_ctx)[f4] = s;
}

// ---------------- K4a: hidden = Wv·ctx + bv*psum ----------------
__global__ void __launch_bounds__(256) k_hidden(const float4* __restrict__ Wv4,
                                                const float*  __restrict__ bv){
    int lane = threadIdx.x&31, warp = threadIdx.x>>5;
    int row = blockIdx.x*8+warp;
    int h = row>>6;
    float4 w[8];
    #pragma unroll
    for (int k=0;k<8;k++) w[k] = Wv4[row*256 + lane + 32*k];
    const float4* c4 = (const float4*)g_ctx;
    float acc[8];
    #pragma unroll
    for (int b=0;b<8;b++){
        float s=0.f;
        #pragma unroll
        for (int k=0;k<8;k++){
            float4 c = c4[((b<<4)+h)*256 + lane + 32*k];
            s += w[k].x*c.x + w[k].y*c.y + w[k].z*c.z + w[k].w*c.w;
        }
        acc[b]=s;
    }
    #pragma unroll
    for (int o=16;o;o>>=1)
        #pragma unroll
        for (int b=0;b<8;b++) acc[b] += __shfl_xor_sync(0xffffffffu, acc[b], o);
    if (lane==0){
        float bvr = bv[row];
        #pragma unroll
        for (int b=0;b<8;b++) g_hidden[b*1024+row] = acc[b] + bvr*g_psum[(b<<4)+h];
    }
}

// ---------------- K4c: fused LN + act = relu(ln(hidden) @ W1^T + b1) ----------------
__global__ void __launch_bounds__(256) k_mlp1(const float4* __restrict__ W14,
                                              const float*  __restrict__ b1,
                                              const float4* __restrict__ lg4,
                                              const float4* __restrict__ lb4){
    __shared__ float4 hls[2048];   // 8 normalized rows x 1024 floats
    int tid = threadIdx.x, lane=tid&31, warp=tid>>5;
    {   // each warp LayerNorms batch row b=warp
        int b = warp;
        const float4* h4 = (const float4*)g_hidden;
        float4 v[8];
        float s = 0.f;
        #pragma unroll
        for (int k=0;k<8;k++){
            v[k] = h4[b*256 + lane + 32*k];
            s += v[k].x + v[k].y + v[k].z + v[k].w;
        }
        s = warp_sum(s);
        float mu = s * (1.f/1024.f);
        float q = 0.f;
        #pragma unroll
        for (int k=0;k<8;k++){
            float dx=v[k].x-mu, dy=v[k].y-mu, dz=v[k].z-mu, dw=v[k].w-mu;
            q += dx*dx + dy*dy + dz*dz + dw*dw;
        }
        q = warp_sum(q);
        float rstd = rsqrtf(q*(1.f/1024.f) + 1e-5f);
        #pragma unroll
        for (int k=0;k<8;k++){
            float4 g = lg4[lane+32*k], bb = lb4[lane+32*k];
            hls[b*256+lane+32*k] = make_float4(
                (v[k].x-mu)*rstd*g.x + bb.x,
                (v[k].y-mu)*rstd*g.y + bb.y,
                (v[k].z-mu)*rstd*g.z + bb.z,
                (v[k].w-mu)*rstd*g.w + bb.w);
        }
    }
    __syncthreads();
    int row = blockIdx.x*8+warp;
    float4 w[8];
    #pragma unroll
    for (int k=0;k<8;k++) w[k]=W14[row*256+lane+32*k];
    float acc[8];
    #pragma unroll
    for (int b=0;b<8;b++){
        float s=0.f;
        #pragma unroll
        for (int k=0;k<8;k++){
            float4 hv = hls[b*256 + lane + 32*k];
            s += w[k].x*hv.x + w[k].y*hv.y + w[k].z*hv.z + w[k].w*hv.w;
        }
        acc[b]=s;
    }
    #pragma unroll
    for (int o=16;o;o>>=1)
        #pragma unroll
        for (int b=0;b<8;b++) acc[b] += __shfl_xor_sync(0xffffffffu, acc[b], o);
    if (lane==0){
        float bb = b1[row];
        #pragma unroll
        for (int b=0;b<8;b++) g_act[b*4096+row] = fmaxf(acc[b]+bb, 0.f);
    }
}

// ---------------- K4d: out = act @ W2^T + b2 ----------------
__global__ void __launch_bounds__(256) k_mlp2(const float4* __restrict__ W24,
                                              const float*  __restrict__ b2,
                                              float* __restrict__ out){
    extern __shared__ float4 as4[];    // 8x4096 floats = 128KB dynamic
    int tid=threadIdx.x, lane=tid&31, warp=tid>>5;
    const float4* a4 = (const float4*)g_act;
    #pragma unroll
    for (int i=0;i<32;i++) as4[tid+256*i] = a4[tid+256*i];
    __syncthreads();
    int row = blockIdx.x*8+warp;
    float acc[8];
    #pragma unroll
    for (int b=0;b<8;b++) acc[b]=0.f;
    #pragma unroll 4
    for (int k=0;k<32;k++){
        float4 w = W24[row*1024 + lane + 32*k];
        #pragma unroll
        for (int b=0;b<8;b++){
            float4 av = as4[b*1024 + lane + 32*k];
            acc[b] += w.x*av.x + w.y*av.y + w.z*av.z + w.w*av.w;
        }
    }
    #pragma unroll
    for (int o=16;o;o>>=1)
        #pragma unroll
        for (int b=0;b<8;b++) acc[b] += __shfl_xor_sync(0xffffffffu, acc[b], o);
    if (lane==0){
        float bb = b2[row];
        #pragma unroll
        for (int b=0;b<8;b++) out[b*1024+row] = acc[b] + bb;
    }
}

extern "C" void kernel_launch(void* const* d_in, const int* in_sizes, int n_in,
                              void* d_out, int out_size){
    const float* x     = (const float*)d_in[0];
    const float* gu    = (const float*)d_in[1];
    const float* query = (const float*)d_in[2];
    const float* Wq    = (const float*)d_in[3];
    const float* bq    = (const float*)d_in[4];
    const float* Wk    = (const float*)d_in[5];
    const float* bk    = (const float*)d_in[6];
    const float* Wv    = (const float*)d_in[7];
    const float* bv    = (const float*)d_in[8];
    const float* ln_g  = (const float*)d_in[9];
    const float* ln_b  = (const float*)d_in[10];
    const float* W1    = (const float*)d_in[11];
    const float* b1    = (const float*)d_in[12];
    const float* W2    = (const float*)d_in[13];
    const float* b2    = (const float*)d_in[14];
    float* out = (float*)d_out;

    cudaFuncSetAttribute(k_mlp2, cudaFuncAttributeMaxDynamicSharedMemorySize, 131072);

    k_qvec   <<<128,256>>>((const float4*)Wq, (const float4*)query, bq);   // 1
    k_wqk    <<<128,256>>>((const float4*)Wk, bk);                          // 2
    k_dummy  <<<1,32>>>();                                                  // 3
    k_logits <<<1024,256>>>((const float4*)x);                              // 4 (profiled)
    k_softmax<<<128,256>>>((const float2*)gu);                              // 5
    k_sums   <<<128,256>>>(out);                                            // 6
    k_ctx    <<<128,256>>>((const float4*)x);                               // 7
    k_ctxr   <<<128,256>>>();                                               // 8
    k_hidden <<<128,256>>>((const float4*)Wv, bv);                          // 9
    k_mlp1   <<<512,256>>>((const float4*)W1, b1,
                           (const float4*)ln_g, (const float4*)ln_b);       // 10
    k_mlp2   <<<128,256,131072>>>((const float4*)W2, b2, out);              // 11
}

// round 5
// speedup vs baseline: 1.2308x; 1.2308x over previous
#include <cuda_runtime.h>
#include <math.h>

typedef unsigned long long ull;

// Problem constants
#define NB 8
#define SQ 4096
#define EE 1024
#define HH 16
#define NCHUNK 32
#define CHUNK 128

// Scratch (static device globals -- allocation-free per harness rules)
__device__ float g_qvec[EE];
__device__ float g_wqk[HH*EE];
__device__ float g_c[HH];
__device__ float g_logits[NB*HH*SQ];
__device__ float g_pm[NB*HH*SQ];
__device__ float g_A[NB*HH*SQ];
__device__ float g_psum[NB*HH];
__device__ float g_partial[NB*NCHUNK*HH*EE];   // 16.8 MB partial ctx
__device__ float g_ctx[NB*HH*EE];
__device__ float g_hidden[NB*EE];
__device__ float g_act[NB*4*EE];

__device__ __forceinline__ float warp_sum(float v){
    #pragma unroll
    for (int o=16;o;o>>=1) v += __shfl_xor_sync(0xffffffffu, v, o);
    return v;
}

// packed f32x2 helpers
__device__ __forceinline__ void ffma2(ull &d, ull a, ull b){
    asm("fma.rn.f32x2 %0, %1, %2, %0;" : "+l"(d) : "l"(a), "l"(b));
}
__device__ __forceinline__ ull fadd2(ull a, ull b){
    ull d; asm("add.rn.f32x2 %0, %1, %2;" : "=l"(d) : "l"(a), "l"(b)); return d;
}
__device__ __forceinline__ ull pk2(float x, float y){
    float2 t = make_float2(x,y); return *(ull*)&t;
}
__device__ __forceinline__ float2 upk(ull v){ return *(float2*)&v; }

__device__ __forceinline__ void cpa16(void* s, const void* g){
    unsigned sa = (unsigned)__cvta_generic_to_shared(s);
    asm volatile("cp.async.cg.shared.global [%0],[%1],16;"::"r"(sa),"l"(g));
}

__global__ void k_dummy(){}

// ---------------- K0a: qvec = Wq @ query + bq ----------------
__global__ void __launch_bounds__(256) k_qvec(const float4* __restrict__ Wq4,
                                              const float4* __restrict__ q4,
                                              const float*  __restrict__ bq){
    int lane = threadIdx.x & 31, warp = threadIdx.x >> 5;
    int row = blockIdx.x*8 + warp;
    float acc = 0.f;
    #pragma unroll
    for (int k=0;k<8;k++){
        float4 w = Wq4[row*256 + lane + 32*k];
        float4 q = q4[lane + 32*k];
        acc += w.x*q.x + w.y*q.y + w.z*q.z + w.w*q.w;
    }
    acc = warp_sum(acc);
    if (lane==0) g_qvec[row] = acc + bq[row];
}

// ---------------- K0b: w_qk[h,e] = 0.125*sum_d qv[d]*Wk[h*64+d,e]; c[h] ----------------
__global__ void __launch_bounds__(256) k_wqk(const float4* __restrict__ Wk4,
                                             const float*  __restrict__ bk){
    __shared__ float qv[64];
    __shared__ float4 red[8][32];
    int h = blockIdx.x>>3, es = blockIdx.x&7;
    int tid = threadIdx.x, col = tid&31, dg = tid>>5;
    if (tid < 64) qv[tid] = g_qvec[h*64+tid];
    __syncthreads();
    float4 acc = make_float4(0.f,0.f,0.f,0.f);
    #pragma unroll
    for (int j=0;j<8;j++){
        int d = dg*8+j;
        float w = qv[d];
        float4 kk = Wk4[(h*64+d)*256 + es*32 + col];
        acc.x += w*kk.x; acc.y += w*kk.y; acc.z += w*kk.z; acc.w += w*kk.w;
    }
    red[dg][col] = acc;
    __syncthreads();
    if (tid < 32){
        float4 s = red[0][tid];
        #pragma unroll
        for (int g=1;g<8;g++){
            float4 r = red[g][tid];
            s.x+=r.x; s.y+=r.y; s.z+=r.z; s.w+=r.w;
        }
        s.x*=0.125f; s.y*=0.125f; s.z*=0.125f; s.w*=0.125f;
        ((float4*)g_wqk)[h*256 + es*32 + tid] = s;
    }
    if (es==0 && tid==0){
        float c=0.f;
        for (int d=0;d<64;d++) c += qv[d]*bk[h*64+d];
        g_c[h] = 0.125f*c;
    }
}

// ---------------- K1: logits = w_qk·x + c ----------------
// warp -> 128-float e-slice. lane&15 = head, lane>>4 = interleave group.
// Thread: 1 head x 64 e-floats (16 float4 interleaved by 2), acc = 4 rows only.
// Reduction: 1 shfl xor16 + 8-warp smem combine.
__global__ void __launch_bounds__(256,2) k_logits(const float4* __restrict__ x4){
    __shared__ float4 sxf[2][1024];     // 32KB double buffer, 4 rows x 1KB
    __shared__ float  sred[8*16*4];     // [warp][head][row]
    int tid = threadIdx.x, lane = tid&31, warp = tid>>5;
    int h = lane&15, g = lane>>4;
    // weights: head h, e-float4 indices warp*32 + 2k + g
    ull wa[16], wb[16];
    {
        const float4* wq4 = (const float4*)g_wqk;
        #pragma unroll
        for (int k=0;k<16;k++){
            float4 t = wq4[h*256 + warp*32 + 2*k + g];
            wa[k] = pk2(t.x,t.y);
            wb[k] = pk2(t.z,t.w);
        }
    }
    int rowbase = blockIdx.x*32;
    int b = rowbase>>12;

    // prefetch tile 0 (4 rows)
    #pragma unroll
    for (int i=0;i<4;i++) cpa16(&sxf[0][i*256+tid], &x4[(rowbase+i)*256 + tid]);
    asm volatile("cp.async.commit_group;");

    for (int t=0;t<8;t++){
        if (t<7){
            int rb1 = rowbase + (t+1)*4;
            #pragma unroll
            for (int i=0;i<4;i++) cpa16(&sxf[(t+1)&1][i*256+tid], &x4[(rb1+i)*256 + tid]);
            asm volatile("cp.async.commit_group;");
            asm volatile("cp.async.wait_group 1;");
        } else {
            asm volatile("cp.async.wait_group 0;");
        }
        __syncthreads();
        const ulonglong2* xs = (const ulonglong2*)sxf[t&1];
        ull acc[4];
        #pragma unroll
        for (int r=0;r<4;r++) acc[r] = 0ULL;
        #pragma unroll
        for (int k=0;k<16;k++){
            #pragma unroll
            for (int r=0;r<4;r++){
                ulonglong2 xu = xs[r*256 + warp*32 + 2*k + g];
                ffma2(acc[r], wa[k], xu.x);
                ffma2(acc[r], wb[k], xu.y);
            }
        }
        // combine the two interleave groups: xor 16
        float4 v;
        {
            ull a0 = fadd2(acc[0], __shfl_xor_sync(0xffffffffu, acc[0], 16));
            ull a1 = fadd2(acc[1], __shfl_xor_sync(0xffffffffu, acc[1], 16));
            ull a2 = fadd2(acc[2], __shfl_xor_sync(0xffffffffu, acc[2], 16));
            ull a3 = fadd2(acc[3], __shfl_xor_sync(0xffffffffu, acc[3], 16));
            float2 f0=upk(a0), f1=upk(a1), f2=upk(a2), f3=upk(a3);
            v = make_float4(f0.x+f0.y, f1.x+f1.y, f2.x+f2.y, f3.x+f3.y);
        }
        if (g==0) *(float4*)&sred[warp*64 + h*4] = v;
        __syncthreads();
        if (tid < 64){
            int hh = tid>>2, r = tid&3;
            float s = 0.f;
            #pragma unroll
            for (int w=0;w<8;w++) s += sred[w*64 + hh*4 + r];
            int row = rowbase + t*4 + r;
            g_logits[((b<<4)+hh)*4096 + (row & 4095)] = s + g_c[hh];
        }
        __syncthreads();
    }
}

// ---------------- K2: softmax over S + gumbel hard mask, per (b,h) ----------------
__global__ void __launch_bounds__(256) k_softmax(const float2* __restrict__ gu2){
    __shared__ float red[8];
    __shared__ float bc;
    int bid = blockIdx.x;                 // b*16+h
    int tid = threadIdx.x, lane = tid&31, warp = tid>>5;
    int base = bid*4096;
    float l[16];
    float m = -1e30f;
    #pragma unroll
    for (int j=0;j<16;j++){ l[j] = g_logits[base + tid + 256*j]; m = fmaxf(m, l[j]); }
    #pragma unroll
    for (int o=16;o;o>>=1) m = fmaxf(m, __shfl_xor_sync(0xffffffffu,m,o));
    if (lane==0) red[warp]=m;
    __syncthreads();
    if (tid==0){ float mm=red[0]; for(int i=1;i<8;i++) mm=fmaxf(mm,red[i]); bc=mm; }
    __syncthreads();
    m = bc;
    float ex[16]; float sum=0.f;
    #pragma unroll
    for (int j=0;j<16;j++){ ex[j]=__expf(l[j]-m); sum+=ex[j]; }
    sum = warp_sum(sum);
    if (lane==0) red[warp]=sum;
    __syncthreads();
    if (tid==0){ float ss=0.f; for(int i=0;i<8;i++) ss+=red[i]; bc=ss; }
    __syncthreads();
    float inv = 1.f/bc;
    float ps=0.f;
    #pragma unroll
    for (int j=0;j<16;j++){
        int s = tid+256*j;
        float prob = ex[j]*inv;
        float2 u = gu2[base+s];
        float g0 = -__logf(-__logf(u.x+1e-20f)+1e-20f);
        float g1 = -__logf(-__logf(u.y+1e-20f)+1e-20f);
        float A = (l[j]+g1 > g0) ? 1.f : 0.f;
        float pm = A*prob;
        g_A[base+s]=A; g_pm[base+s]=pm; ps+=pm;
    }
    ps = warp_sum(ps);
    if (lane==0) red[warp]=ps;
    __syncthreads();
    if (tid==0){ float ss=0.f; for(int i=0;i<8;i++) ss+=red[i]; g_psum[bid]=ss; }
}

// ---------------- K2b: masks/attn = sum over heads (float4, h quartered) ----------------
__global__ void __launch_bounds__(256) k_sums(float* __restrict__ out){
    __shared__ float4 sA[4][64], sP[4][64];
    int tid = threadIdx.x;
    int t = tid>>2, q = tid&3;
    int sf4 = blockIdx.x*64 + t;         // global s-float4 index (0..8191)
    int b = sf4>>10, f = sf4&1023;
    const float4* A4 = (const float4*)g_A;
    const float4* P4 = (const float4*)g_pm;
    float4 ms = make_float4(0,0,0,0), as = make_float4(0,0,0,0);
    #pragma unroll
    for (int hh=0; hh<4; hh++){
        int h = q*4+hh;
        int off = ((b<<4)+h)*1024 + f;
        float4 av = A4[off], pv = P4[off];
        ms.x+=av.x; ms.y+=av.y; ms.z+=av.z; ms.w+=av.w;
        as.x+=pv.x; as.y+=pv.y; as.z+=pv.z; as.w+=pv.w;
    }
    if (q){ sA[q][t]=ms; sP[q][t]=as; }
    __syncthreads();
    if (q==0){
        #pragma unroll
        for (int g=1;g<4;g++){
            float4 av = sA[g][t], pv = sP[g][t];
            ms.x+=av.x; ms.y+=av.y; ms.z+=av.z; ms.w+=av.w;
            as.x+=pv.x; as.y+=pv.y; as.z+=pv.z; as.w+=pv.w;
        }
        float4* out4 = (float4*)out;
        out4[2048 + sf4] = ms;           // masks @ out[8192]
        out4[10240 + sf4] = as;          // attn  @ out[40960]
    }
}

// ---------------- K3: ctx partials (pass 2 over x), grid 256 (full chip) ----------------
// spm relayout [si][2h..] padded stride 36 floats: one LDS.128 = 2 heads' packed p.
__global__ void __launch_bounds__(256,2) k_ctx(const ulonglong2* __restrict__ xg){
    __shared__ __align__(16) float sp[CHUNK*36];   // 18KB
    int tid = threadIdx.x;
    int b = blockIdx.x >> 5, chunk = blockIdx.x & 31;
    int s0 = chunk*CHUNK;
    #pragma unroll
    for (int i=0;i<8;i++){
        int idx = tid + 256*i;           // 2048 = 16h x 128si
        int h = idx>>7, si = idx&127;
        float p = g_pm[((b<<4)+h)*4096 + s0 + si];
        *(float2*)&sp[si*36 + 2*h] = make_float2(p,p);
    }
    __syncthreads();
    ull acc[16][2];
    #pragma unroll
    for (int h=0;h<16;h++){ acc[h][0]=0ULL; acc[h][1]=0ULL; }
    #pragma unroll 2
    for (int si=0; si<CHUNK; si++){
        ulonglong2 xu = xg[(b*4096 + s0 + si)*256 + tid];
        #pragma unroll
        for (int hp=0;hp<8;hp++){
            ulonglong2 pu = *(const ulonglong2*)&sp[si*36 + 4*hp];
            ffma2(acc[2*hp  ][0], pu.x, xu.x);
            ffma2(acc[2*hp  ][1], pu.x, xu.y);
            ffma2(acc[2*hp+1][0], pu.y, xu.x);
            ffma2(acc[2*hp+1][1], pu.y, xu.y);
        }
    }
    ulonglong2* p4 = (ulonglong2*)g_partial;
    #pragma unroll
    for (int h=0;h<16;h++){
        ulonglong2 o; o.x = acc[h][0]; o.y = acc[h][1];
        p4[((b*NCHUNK+chunk)*16 + h)*256 + tid] = o;
    }
}

// ---------------- K3r: deterministic reduction of ctx partials (float4) ----------------
__global__ void __launch_bounds__(256) k_ctxr(){
    int f4 = blockIdx.x*256 + threadIdx.x;   // 0..32767 float4 of ctx
    int b = f4>>12, rem = f4&4095;
    const float4* p4 = (const float4*)g_partial;
    float4 s = make_float4(0,0,0,0);
    #pragma unroll
    for (int c=0;c<NCHUNK;c++){
        float4 v = p4[((b*NCHUNK+c)<<12) + rem];
        s.x+=v.x; s.y+=v.y; s.z+=v.z; s.w+=v.w;
    }
    ((float4*)g_ctx)[f4] = s;
}

// ---------------- K4a: hidden = Wv·ctx + bv*psum ----------------
__global__ void __launch_bounds__(256) k_hidden(const float4* __restrict__ Wv4,
                                                const float*  __restrict__ bv){
    int lane = threadIdx.x&31, warp = threadIdx.x>>5;
    int row = blockIdx.x*8+warp;
    int h = row>>6;
    float4 w[8];
    #pragma unroll
    for (int k=0;k<8;k++) w[k] = Wv4[row*256 + lane + 32*k];
    const float4* c4 = (const float4*)g_ctx;
    float acc[8];
    #pragma unroll
    for (int b=0;b<8;b++){
        float s=0.f;
        #pragma unroll
        for (int k=0;k<8;k++){
            float4 c = c4[((b<<4)+h)*256 + lane + 32*k];
            s += w[k].x*c.x + w[k].y*c.y + w[k].z*c.z + w[k].w*c.w;
        }
        acc[b]=s;
    }
    #pragma unroll
    for (int o=16;o;o>>=1)
        #pragma unroll
        for (int b=0;b<8;b++) acc[b] += __shfl_xor_sync(0xffffffffu, acc[b], o);
    if (lane==0){
        float bvr = bv[row];
        #pragma unroll
        for (int b=0;b<8;b++) g_hidden[b*1024+row] = acc[b] + bvr*g_psum[(b<<4)+h];
    }
}

// ---------------- K4c: fused LN + act = relu(ln(hidden) @ W1^T + b1) ----------------
__global__ void __launch_bounds__(256) k_mlp1(const float4* __restrict__ W14,
                                              const float*  __restrict__ b1,
                                              const float4* __restrict__ lg4,
                                              const float4* __restrict__ lb4){
    __shared__ float4 hls[2048];   // 8 normalized rows x 1024 floats
    int tid = threadIdx.x, lane=tid&31, warp=tid>>5;
    {   // each warp LayerNorms batch row b=warp
        int b = warp;
        const float4* h4 = (const float4*)g_hidden;
        float4 v[8];
        float s = 0.f;
        #pragma unroll
        for (int k=0;k<8;k++){
            v[k] = h4[b*256 + lane + 32*k];
            s += v[k].x + v[k].y + v[k].z + v[k].w;
        }
        s = warp_sum(s);
        float mu = s * (1.f/1024.f);
        float q = 0.f;
        #pragma unroll
        for (int k=0;k<8;k++){
            float dx=v[k].x-mu, dy=v[k].y-mu, dz=v[k].z-mu, dw=v[k].w-mu;
            q += dx*dx + dy*dy + dz*dz + dw*dw;
        }
        q = warp_sum(q);
        float rstd = rsqrtf(q*(1.f/1024.f) + 1e-5f);
        #pragma unroll
        for (int k=0;k<8;k++){
            float4 g = lg4[lane+32*k], bb = lb4[lane+32*k];
            hls[b*256+lane+32*k] = make_float4(
                (v[k].x-mu)*rstd*g.x + bb.x,
                (v[k].y-mu)*rstd*g.y + bb.y,
                (v[k].z-mu)*rstd*g.z + bb.z,
                (v[k].w-mu)*rstd*g.w + bb.w);
        }
    }
    __syncthreads();
    int row = blockIdx.x*8+warp;
    float4 w[8];
    #pragma unroll
    for (int k=0;k<8;k++) w[k]=W14[row*256+lane+32*k];
    float acc[8];
    #pragma unroll
    for (int b=0;b<8;b++){
        float s=0.f;
        #pragma unroll
        for (int k=0;k<8;k++){
            float4 hv = hls[b*256 + lane + 32*k];
            s += w[k].x*hv.x + w[k].y*hv.y + w[k].z*hv.z + w[k].w*hv.w;
        }
        acc[b]=s;
    }
    #pragma unroll
    for (int o=16;o;o>>=1)
        #pragma unroll
        for (int b=0;b<8;b++) acc[b] += __shfl_xor_sync(0xffffffffu, acc[b], o);
    if (lane==0){
        float bb = b1[row];
        #pragma unroll
        for (int b=0;b<8;b++) g_act[b*4096+row] = fmaxf(acc[b]+bb, 0.f);
    }
}

// ---------------- K4d: out = act @ W2^T + b2 ----------------
__global__ void __launch_bounds__(256) k_mlp2(const float4* __restrict__ W24,
                                              const float*  __restrict__ b2,
                                              float* __restrict__ out){
    extern __shared__ float4 as4[];    // 8x4096 floats = 128KB dynamic
    int tid=threadIdx.x, lane=tid&31, warp=tid>>5;
    const float4* a4 = (const float4*)g_act;
    #pragma unroll
    for (int i=0;i<32;i++) as4[tid+256*i] = a4[tid+256*i];
    __syncthreads();
    int row = blockIdx.x*8+warp;
    float acc[8];
    #pragma unroll
    for (int b=0;b<8;b++) acc[b]=0.f;
    #pragma unroll 4
    for (int k=0;k<32;k++){
        float4 w = W24[row*1024 + lane + 32*k];
        #pragma unroll
        for (int b=0;b<8;b++){
            float4 av = as4[b*1024 + lane + 32*k];
            acc[b] += w.x*av.x + w.y*av.y + w.z*av.z + w.w*av.w;
        }
    }
    #pragma unroll
    for (int o=16;o;o>>=1)
        #pragma unroll
        for (int b=0;b<8;b++) acc[b] += __shfl_xor_sync(0xffffffffu, acc[b], o);
    if (lane==0){
        float bb = b2[row];
        #pragma unroll
        for (int b=0;b<8;b++) out[b*1024+row] = acc[b] + bb;
    }
}

extern "C" void kernel_launch(void* const* d_in, const int* in_sizes, int n_in,
                              void* d_out, int out_size){
    const float* x     = (const float*)d_in[0];
    const float* gu    = (const float*)d_in[1];
    const float* query = (const float*)d_in[2];
    const float* Wq    = (const float*)d_in[3];
    const float* bq    = (const float*)d_in[4];
    const float* Wk    = (const float*)d_in[5];
    const float* bk    = (const float*)d_in[6];
    const float* Wv    = (const float*)d_in[7];
    const float* bv    = (const float*)d_in[8];
    const float* ln_g  = (const float*)d_in[9];
    const float* ln_b  = (const float*)d_in[10];
    const float* W1    = (const float*)d_in[11];
    const float* b1    = (const float*)d_in[12];
    const float* W2    = (const float*)d_in[13];
    const float* b2    = (const float*)d_in[14];
    float* out = (float*)d_out;

    cudaFuncSetAttribute(k_mlp2, cudaFuncAttributeMaxDynamicSharedMemorySize, 131072);

    k_qvec   <<<128,256>>>((const float4*)Wq, (const float4*)query, bq);   // 1
    k_wqk    <<<128,256>>>((const float4*)Wk, bk);                          // 2
    k_dummy  <<<1,32>>>();                                                  // 3
    k_logits <<<1024,256>>>((const float4*)x);                              // 4 (profiled)
    k_softmax<<<128,256>>>((const float2*)gu);                              // 5
    k_sums   <<<128,256>>>(out);                                            // 6
    k_ctx    <<<256,256>>>((const ulonglong2*)x);                           // 7
    k_ctxr   <<<128,256>>>();                                               // 8
    k_hidden <<<128,256>>>((const float4*)Wv, bv);                          // 9
    k_mlp1   <<<512,256>>>((const float4*)W1, b1,
                           (const float4*)ln_g, (const float4*)ln_b);       // 10
    k_mlp2   <<<128,256,131072>>>((const float4*)W2, b2, out);              // 11
}